// round 1
// baseline (speedup 1.0000x reference)
#include <cuda_runtime.h>
#include <math.h>
#include <stdint.h>

// Problem constants
#define NTOK   8192          // B*T
#define DDIM   1024
#define NEXP   8
#define HDIM   2048
#define TOPK   2
#define NPAIR  (NTOK * TOPK) // 16384 routed (token, slot) pairs

// Output buffer layout (flattened reference return tuple, fp32)
#define OUT_OFF   ((size_t)0)
#define OUT_SZ    ((size_t)NTOK * DDIM)                 // 8388608
#define AUX_OFF   (OUT_OFF + OUT_SZ)                    // 8388608
#define PROBS_OFF (AUX_OFF + 1)                         // 8388609
#define IDX_OFF   (PROBS_OFF + (size_t)NTOK * NEXP)     // 8454145
#define TP_OFF    (IDX_OFF + (size_t)NTOK * TOPK)       // 8470529

// Device scratch (static globals: allocation-free per harness rules)
__device__ float g_h[(size_t)NPAIR * HDIM];   // gelu(x @ w1) per routed pair (134 MB)
__device__ float g_y[(size_t)NPAIR * DDIM];   // (h @ w2) per routed pair (67 MB)
__device__ int   g_list[NEXP * NTOK];         // per-expert routed pair ids
__device__ int   g_count[NEXP];
__device__ float g_probsum[NEXP];

__device__ __forceinline__ float gelu_exact(float v) {
    return 0.5f * v * (1.0f + erff(v * 0.70710678118654752f));
}

// ---------------------------------------------------------------------------
// Zero per-launch accumulators (graph replays must be self-contained)
// ---------------------------------------------------------------------------
__global__ void zero_kernel() {
    int t = threadIdx.x;
    if (t < NEXP) { g_count[t] = 0; g_probsum[t] = 0.f; }
}

// ---------------------------------------------------------------------------
// Router: one warp per token. logits -> softmax -> top2 -> renorm.
// Writes probs / idx / topk_probs to output tail; builds expert lists.
// ---------------------------------------------------------------------------
__global__ __launch_bounds__(256) void router_kernel(
    const float* __restrict__ x, const float* __restrict__ gw,
    float* __restrict__ out)
{
    __shared__ float sprob[NEXP];
    int tid = threadIdx.x;
    if (tid < NEXP) sprob[tid] = 0.f;
    __syncthreads();

    int tok  = (blockIdx.x * blockDim.x + tid) >> 5;
    int lane = tid & 31;

    if (tok < NTOK) {
        const float* xr = x + (size_t)tok * DDIM;
        float acc[NEXP];
#pragma unroll
        for (int e = 0; e < NEXP; e++) acc[e] = 0.f;
        for (int d = lane; d < DDIM; d += 32) {
            float xv = xr[d];
            const float* g = gw + (size_t)d * NEXP;
#pragma unroll
            for (int e = 0; e < NEXP; e++) acc[e] += xv * g[e];
        }
#pragma unroll
        for (int off = 16; off > 0; off >>= 1)
#pragma unroll
            for (int e = 0; e < NEXP; e++)
                acc[e] += __shfl_down_sync(0xffffffffu, acc[e], off);

        if (lane == 0) {
            float mx = acc[0];
#pragma unroll
            for (int e = 1; e < NEXP; e++) mx = fmaxf(mx, acc[e]);
            float p[NEXP], s = 0.f;
#pragma unroll
            for (int e = 0; e < NEXP; e++) { p[e] = __expf(acc[e] - mx); s += p[e]; }
            float inv = 1.f / s;
#pragma unroll
            for (int e = 0; e < NEXP; e++) {
                p[e] *= inv;
                out[PROBS_OFF + (size_t)tok * NEXP + e] = p[e];
                atomicAdd(&sprob[e], p[e]);
            }
            // top-2, first-index-wins on ties (jax top_k semantics)
            int i0 = 0;
#pragma unroll
            for (int e = 1; e < NEXP; e++) if (p[e] > p[i0]) i0 = e;
            int i1 = -1;
#pragma unroll
            for (int e = 0; e < NEXP; e++)
                if (e != i0 && (i1 < 0 || p[e] > p[i1])) i1 = e;
            float ps  = p[i0] + p[i1];
            float w0  = p[i0] / ps;
            float w1v = p[i1] / ps;
            out[IDX_OFF + (size_t)tok * 2 + 0] = (float)i0;
            out[IDX_OFF + (size_t)tok * 2 + 1] = (float)i1;
            out[TP_OFF  + (size_t)tok * 2 + 0] = w0;
            out[TP_OFF  + (size_t)tok * 2 + 1] = w1v;
            int pos0 = atomicAdd(&g_count[i0], 1);
            g_list[i0 * NTOK + pos0] = tok * 2 + 0;
            int pos1 = atomicAdd(&g_count[i1], 1);
            g_list[i1 * NTOK + pos1] = tok * 2 + 1;
        }
    }
    __syncthreads();
    if (tid < NEXP) atomicAdd(&g_probsum[tid], sprob[tid]);
}

// ---------------------------------------------------------------------------
// Grouped expert GEMM, 128x128x8 SGEMM tile, 8x8 per thread, gathered A rows.
// STAGE 1: A row = x[pair>>1], W = w1[e] (D x H), Out = g_h (+gelu)
// STAGE 2: A row = g_h[pair],  W = w2[e] (H x D), Out = g_y
// grid = (ND/128, NTOK/128, NEXP); blocks past g_count[e] exit early.
// ---------------------------------------------------------------------------
#define BM 128
#define BN 128
#define BK 8

template <int STAGE>
__global__ __launch_bounds__(256) void expert_gemm(
    const float* __restrict__ X, const float* __restrict__ Wfull)
{
    constexpr int KD = (STAGE == 1) ? DDIM : HDIM;
    constexpr int ND = (STAGE == 1) ? HDIM : DDIM;

    int e   = blockIdx.z;
    int cnt = g_count[e];
    int row0 = blockIdx.y * BM;
    if (row0 >= cnt) return;
    int col0 = blockIdx.x * BN;

    const float* A_src = (STAGE == 1) ? X : g_h;
    float*       Out   = (STAGE == 1) ? g_h : g_y;
    const float* Wb    = Wfull + (size_t)e * KD * ND;
    const int*   list  = g_list + e * NTOK;

    __shared__ float As[BK][BM];
    __shared__ float Bs[BK][BN];
    __shared__ int   rowp[BM];

    int tid = threadIdx.x;
    if (tid < BM) {
        int m = row0 + tid;
        rowp[tid] = (m < cnt) ? list[m] : -1;
    }
    __syncthreads();

    int am  = tid >> 1;          // 0..127  A row within tile
    int ak  = (tid & 1) * 4;     // 0 or 4
    int bkr = tid >> 5;          // 0..7    B k-row
    int bn  = (tid & 31) * 4;    // B col within tile
    int tx  = tid & 15;
    int ty  = tid >> 4;

    // Precompute gathered A row pointer for this thread's load role
    const float* arow = nullptr;
    {
        int p = rowp[am];
        if (p >= 0) {
            size_t r = (STAGE == 1) ? (size_t)(p >> 1) : (size_t)p;
            arow = A_src + r * KD;
        }
    }

    float acc[8][8];
#pragma unroll
    for (int i = 0; i < 8; i++)
#pragma unroll
        for (int j = 0; j < 8; j++) acc[i][j] = 0.f;

    for (int kt = 0; kt < KD; kt += BK) {
        float4 av = make_float4(0.f, 0.f, 0.f, 0.f);
        if (arow) av = *reinterpret_cast<const float4*>(arow + kt + ak);
        As[ak + 0][am] = av.x;
        As[ak + 1][am] = av.y;
        As[ak + 2][am] = av.z;
        As[ak + 3][am] = av.w;

        float4 bv = *reinterpret_cast<const float4*>(
            Wb + (size_t)(kt + bkr) * ND + col0 + bn);
        *reinterpret_cast<float4*>(&Bs[bkr][bn]) = bv;
        __syncthreads();

#pragma unroll
        for (int k = 0; k < BK; k++) {
            float a[8], b[8];
            *reinterpret_cast<float4*>(&a[0]) =
                *reinterpret_cast<const float4*>(&As[k][ty * 8]);
            *reinterpret_cast<float4*>(&a[4]) =
                *reinterpret_cast<const float4*>(&As[k][ty * 8 + 4]);
            *reinterpret_cast<float4*>(&b[0]) =
                *reinterpret_cast<const float4*>(&Bs[k][tx * 8]);
            *reinterpret_cast<float4*>(&b[4]) =
                *reinterpret_cast<const float4*>(&Bs[k][tx * 8 + 4]);
#pragma unroll
            for (int i = 0; i < 8; i++)
#pragma unroll
                for (int j = 0; j < 8; j++) acc[i][j] += a[i] * b[j];
        }
        __syncthreads();
    }

#pragma unroll
    for (int i = 0; i < 8; i++) {
        int m = ty * 8 + i;
        int p = rowp[m];
        if (p < 0) continue;
        float* orow = Out + (size_t)p * ND + col0 + tx * 8;
        float v[8];
#pragma unroll
        for (int j = 0; j < 8; j++) {
            float t = acc[i][j];
            v[j] = (STAGE == 1) ? gelu_exact(t) : t;
        }
        *reinterpret_cast<float4*>(orow)     = *reinterpret_cast<float4*>(&v[0]);
        *reinterpret_cast<float4*>(orow + 4) = *reinterpret_cast<float4*>(&v[4]);
    }
}

// ---------------------------------------------------------------------------
// Combine: out[n,d] = w0 * y[2n,d] + w1 * y[2n+1,d]
// ---------------------------------------------------------------------------
__global__ __launch_bounds__(256) void combine_kernel(float* __restrict__ out) {
    size_t idx = (size_t)blockIdx.x * blockDim.x + threadIdx.x;
    if (idx >= OUT_SZ) return;
    size_t n = idx >> 10;        // / DDIM
    size_t d = idx & 1023;
    float w0 = out[TP_OFF + n * 2 + 0];
    float w1 = out[TP_OFF + n * 2 + 1];
    float y0 = g_y[(size_t)(2 * n)     * DDIM + d];
    float y1 = g_y[(size_t)(2 * n + 1) * DDIM + d];
    out[OUT_OFF + idx] = w0 * y0 + w1 * y1;
}

// ---------------------------------------------------------------------------
// Aux loss: E * sum_e (count_e / N) * (mean_prob_e)
// ---------------------------------------------------------------------------
__global__ void aux_kernel(float* __restrict__ out) {
    if (threadIdx.x == 0) {
        float s = 0.f;
#pragma unroll
        for (int e = 0; e < NEXP; e++)
            s += ((float)g_count[e] / (float)NTOK) * (g_probsum[e] / (float)NTOK);
        out[AUX_OFF] = (float)NEXP * s;
    }
}

// ---------------------------------------------------------------------------
extern "C" void kernel_launch(void* const* d_in, const int* in_sizes, int n_in,
                              void* d_out, int out_size) {
    const float* x   = (const float*)d_in[0];   // [B,T,D]
    const float* gw  = (const float*)d_in[1];   // [D,E]
    const float* w1  = (const float*)d_in[2];   // [E,D,H]
    const float* w2  = (const float*)d_in[3];   // [E,H,D]
    float* out = (float*)d_out;

    zero_kernel<<<1, 32>>>();
    router_kernel<<<(NTOK * 32) / 256, 256>>>(x, gw, out);

    dim3 g1(HDIM / BN, NTOK / BM, NEXP);
    expert_gemm<1><<<g1, 256>>>(x, w1);

    dim3 g2(DDIM / BN, NTOK / BM, NEXP);
    expert_gemm<2><<<g2, 256>>>(nullptr, w2);

    combine_kernel<<<(unsigned)((OUT_SZ + 255) / 256), 256>>>(out);
    aux_kernel<<<1, 32>>>(out);
}

// round 12
// speedup vs baseline: 2.5706x; 2.5706x over previous
// =============================================================================
// Round 12 theory (comments only, ASCII).
//
// Post-mortem R11: "GB300 container failed twice" is an INFRASTRUCTURE
// failure (broker could not provision the container), not a verdict on the
// kernel -- no compile, no run, no mem checkpoint was ever taken. Per the
// post-mortem matrix this gives zero information about the R11 theory, so
// the correct move is to RESUBMIT THE IDENTICAL KERNEL and actually collect
// the datapoint.
//
// R11/R12 theory (unchanged): satisfy BOTH suspect constraints at once.
//   Session evidence (globals MiB / mem-delta MiB):
//     R1 192/pass  R4 352/pass  R3 352/384  R6 208/256  R7 208/254
//     R8 208/256   R9 352/384 (GEMM verbatim R4)  R10 160/254
//   R9 tripping with R4's exact GEMM means the spill/footprint behavior is
//   not purely a function of my code shape; cover both hypotheses:
//   1. Tiny global footprint: only g_h (fp16, 64 MiB) + lists. fp16 mantissa
//      == tf32 mantissa and tf32(fp32(h16)) is exact, so stage-2 math is
//      unchanged vs the validated R4 numerics. A and B operands tf32-rounded
//      IN REGISTER from raw inputs (cvt.rna at fragment load); stage 2
//      scatters directly into out[] via atomicAdd (exactly 2 commutative
//      fp32 adds per element -> bitwise deterministic across replays; OUT
//      region zeroed at the start of every launch).
//   2. Low register pressure: CTA 128x64x32, 8 warps (4x2), warp tile 32x32
//      -> acc[2][4][4] = 16 fp32/thread, ~80-100 regs total, far from any
//      spill cliff; also 2-3 CTAs/SM vs R4's 1 (R4 profile: latency-bound,
//      occ 11.9%, tensor 23-28%), so perf should improve even with the
//      smaller tile. Double-buffered cp.async in R4's proven control shape.
//      SMEM A [128][36]f32 (s1) / [128][40]f16 (s2), B [32][72]f32 from
//      untransposed weights; fragment word indices are permutations mod 32
//      -> bank-conflict-free.
//
// Prediction: PASS, delta=0. Stage1 ~300-380us, stage2 ~180-240us, router
// ~40us, zero/aux ~10us -> total ~600-750us; rel_err ~3.5e-4. ncu: mma_gemm
// occ ~25%, tensor 25-40%. Then next rounds step the tile back up toward
// 128x128 to locate the env's actual spill cliff.
// =============================================================================
#include <cuda_runtime.h>
#include <cuda_fp16.h>
#include <math.h>
#include <stdint.h>

#define NTOK   8192
#define DDIM   1024
#define NEXP   8
#define HDIM   2048
#define NPAIR  (NTOK * 2)

#define OUT_OFF   ((size_t)0)
#define OUT_SZ    ((size_t)NTOK * DDIM)
#define AUX_OFF   (OUT_OFF + OUT_SZ)
#define PROBS_OFF (AUX_OFF + 1)
#define IDX_OFF   (PROBS_OFF + (size_t)NTOK * NEXP)
#define TP_OFF    (IDX_OFF + (size_t)NTOK * 2)

// ---- device scratch: 64.3 MiB total ----
__device__ __half g_h[(size_t)NPAIR * HDIM];   // 64 MiB, expert-sorted hidden
__device__ int    g_list[NEXP * NTOK];         // pid = tok*2+slot per expert
__device__ int    g_count[NEXP];
__device__ int    g_off[NEXP];
__device__ float  g_probsum[NEXP];

__device__ __forceinline__ float gelu_exact(float v) {
    return 0.5f * v * (1.0f + erff(v * 0.70710678118654752f));
}
__device__ __forceinline__ uint32_t tf32u(float v) {
    uint32_t r;
    asm("cvt.rna.tf32.f32 %0, %1;" : "=r"(r) : "f"(v));
    return r;
}
__device__ __forceinline__ uint32_t s2u(const void* p) {
    uint32_t a;
    asm("{ .reg .u64 t; cvta.to.shared.u64 t, %1; cvt.u32.u64 %0, t; }"
        : "=r"(a) : "l"(p));
    return a;
}
__device__ __forceinline__ void cpa16(uint32_t dst, const void* src) {
    asm volatile("cp.async.cg.shared.global [%0], [%1], 16;"
                 :: "r"(dst), "l"(src) : "memory");
}
__device__ __forceinline__ void mma_tf32(
    float& c0, float& c1, float& c2, float& c3,
    uint32_t a0, uint32_t a1, uint32_t a2, uint32_t a3,
    uint32_t b0, uint32_t b1)
{
    asm volatile(
        "mma.sync.aligned.m16n8k8.row.col.f32.tf32.tf32.f32 "
        "{%0,%1,%2,%3}, {%4,%5,%6,%7}, {%8,%9}, {%0,%1,%2,%3};"
        : "+f"(c0), "+f"(c1), "+f"(c2), "+f"(c3)
        : "r"(a0), "r"(a1), "r"(a2), "r"(a3), "r"(b0), "r"(b1));
}

__global__ void zero_kernel() {
    int t = threadIdx.x;
    if (t < NEXP) { g_count[t] = 0; g_probsum[t] = 0.f; }
}

__global__ __launch_bounds__(256) void zero_out_kernel(float* __restrict__ out) {
    size_t i = (size_t)blockIdx.x * blockDim.x + threadIdx.x;
    if (i < OUT_SZ / 4)
        ((float4*)(out + OUT_OFF))[i] = make_float4(0.f, 0.f, 0.f, 0.f);
}

__global__ void scan_kernel() {
    if (threadIdx.x == 0) {
        int a = 0;
        for (int e = 0; e < NEXP; e++) { g_off[e] = a; a += g_count[e]; }
    }
}

__global__ __launch_bounds__(256) void router_kernel(
    const float* __restrict__ x, const float* __restrict__ gw,
    float* __restrict__ out)
{
    __shared__ float sprob[NEXP];
    int tid = threadIdx.x;
    if (tid < NEXP) sprob[tid] = 0.f;
    __syncthreads();

    int tok  = (blockIdx.x * blockDim.x + tid) >> 5;
    int lane = tid & 31;

    if (tok < NTOK) {
        const float* xr = x + (size_t)tok * DDIM;
        float acc[NEXP];
#pragma unroll
        for (int e = 0; e < NEXP; e++) acc[e] = 0.f;
        for (int d = lane; d < DDIM; d += 32) {
            float xv = xr[d];
            const float* g = gw + (size_t)d * NEXP;
#pragma unroll
            for (int e = 0; e < NEXP; e++) acc[e] += xv * g[e];
        }
#pragma unroll
        for (int off = 16; off > 0; off >>= 1)
#pragma unroll
            for (int e = 0; e < NEXP; e++)
                acc[e] += __shfl_down_sync(0xffffffffu, acc[e], off);

        if (lane == 0) {
            float mx = acc[0];
#pragma unroll
            for (int e = 1; e < NEXP; e++) mx = fmaxf(mx, acc[e]);
            float p[NEXP], s = 0.f;
#pragma unroll
            for (int e = 0; e < NEXP; e++) { p[e] = __expf(acc[e] - mx); s += p[e]; }
            float inv = 1.f / s;
#pragma unroll
            for (int e = 0; e < NEXP; e++) {
                p[e] *= inv;
                out[PROBS_OFF + (size_t)tok * NEXP + e] = p[e];
                atomicAdd(&sprob[e], p[e]);
            }
            int i0 = 0;
#pragma unroll
            for (int e = 1; e < NEXP; e++) if (p[e] > p[i0]) i0 = e;
            int i1 = -1;
#pragma unroll
            for (int e = 0; e < NEXP; e++)
                if (e != i0 && (i1 < 0 || p[e] > p[i1])) i1 = e;
            float ps  = p[i0] + p[i1];
            out[IDX_OFF + (size_t)tok * 2 + 0] = (float)i0;
            out[IDX_OFF + (size_t)tok * 2 + 1] = (float)i1;
            out[TP_OFF  + (size_t)tok * 2 + 0] = p[i0] / ps;
            out[TP_OFF  + (size_t)tok * 2 + 1] = p[i1] / ps;
            int pos0 = atomicAdd(&g_count[i0], 1);
            g_list[i0 * NTOK + pos0] = tok * 2 + 0;
            int pos1 = atomicAdd(&g_count[i1], 1);
            g_list[i1 * NTOK + pos1] = tok * 2 + 1;
        }
    }
    __syncthreads();
    if (tid < NEXP) atomicAdd(&g_probsum[tid], sprob[tid]);
}

// Grouped GEMM, tf32 mma.sync, CTA 128(M) x 64(N) x 32(K), 8 warps (4x2),
// warp tile 32x32 (acc[2][4][4] = 16 floats/thread). Double-buffered cp.async.
// STAGE 1: A = x rows gathered by pid (fp32), B = w1[e] raw [D][H] -> g_h fp16
// STAGE 2: A = g_h sorted (fp16), B = w2[e] raw [H][D] -> atomicAdd into out
#define BK    32
#define LDA1  36                        // floats
#define LDA2  40                        // halves
#define LDB   72                        // floats
#define ATB1  (128 * LDA1 * 4)          // 18432 bytes
#define ATB2  (128 * LDA2 * 2)          // 10240 bytes
#define BTB   (BK * LDB * 4)            // 9216 bytes
#define DYN1  (2 * (ATB1 + BTB))        // 55296 bytes
#define DYN2  (2 * (ATB2 + BTB))        // 38912 bytes

template <int STAGE>
__global__ __launch_bounds__(256) void mma_gemm(
    const float* __restrict__ Xf, const float* __restrict__ W,
    float* __restrict__ out)
{
    constexpr int KD   = (STAGE == 1) ? DDIM : HDIM;
    constexpr int ND   = (STAGE == 1) ? HDIM : DDIM;
    constexpr int NIT  = KD / BK;
    constexpr int ATB  = (STAGE == 1) ? ATB1 : ATB2;

    int e    = blockIdx.z;
    int cnt  = g_count[e];
    int row0 = blockIdx.y * 128;
    if (row0 >= cnt) return;
    int col0 = blockIdx.x * 64;
    int base = g_off[e];

    extern __shared__ __align__(16) char dyn[];
    uint32_t sb = s2u(dyn);
    // layout: A0 | A1 | B0 | B1
    uint32_t aS[2] = { sb, sb + ATB };
    uint32_t bS[2] = { sb + 2u * ATB, sb + 2u * ATB + BTB };

    int tid  = threadIdx.x;
    int wid  = tid >> 5;
    int lane = tid & 31;
    int g    = lane >> 2;
    int tg   = lane & 3;
    int wm   = (wid >> 1) * 32;   // 4 warp-rows cover M=128
    int wn   = (wid & 1) * 32;    // 2 warp-cols cover N=64

    // ---- load roles ----
    int lrow = tid >> 1;               // 0..127 (A row)
    const float*  arowF = nullptr;
    const __half* arowH = nullptr;
    if (STAGE == 1) {
        int m = row0 + lrow;
        int pid = (m < cnt) ? g_list[e * NTOK + m] : g_list[e * NTOK];
        arowF = Xf + (size_t)(pid >> 1) * DDIM + (tid & 1) * 16;
    } else {
        int m = row0 + lrow;
        size_t r = (m < cnt) ? (size_t)(base + m) : (size_t)base;
        arowH = g_h + r * HDIM + (tid & 1) * 16;
    }
    uint32_t aOff = (STAGE == 1)
        ? (uint32_t)(lrow * LDA1 + (tid & 1) * 16) * 4
        : (uint32_t)(lrow * LDA2 + (tid & 1) * 16) * 2;

    const float* wb = W + (size_t)e * DDIM * HDIM;
    int c0i = tid;                      // B chunk ids: tid and tid+256
    int br0 = c0i >> 4,        bc0 = (c0i & 15) * 4;
    int br1 = (c0i + 256) >> 4, bc1 = ((c0i + 256) & 15) * 4;
    uint32_t bOff0 = (uint32_t)(br0 * LDB + bc0) * 4;
    uint32_t bOff1 = (uint32_t)(br1 * LDB + bc1) * 4;

    float acc[2][4][4];
#pragma unroll
    for (int i = 0; i < 2; i++)
#pragma unroll
        for (int j = 0; j < 4; j++)
#pragma unroll
            for (int c = 0; c < 4; c++) acc[i][j][c] = 0.f;

    // ---- prologue: k-tile 0 into buffer 0 ----
    if (STAGE == 1) {
#pragma unroll
        for (int j = 0; j < 4; j++)
            cpa16(aS[0] + aOff + j * 16, arowF + j * 4);
    } else {
#pragma unroll
        for (int j = 0; j < 2; j++)
            cpa16(aS[0] + aOff + j * 16, arowH + j * 8);
    }
    cpa16(bS[0] + bOff0, wb + (size_t)br0 * ND + col0 + bc0);
    cpa16(bS[0] + bOff1, wb + (size_t)br1 * ND + col0 + bc1);
    asm volatile("cp.async.commit_group;" ::: "memory");

    for (int it = 0; it < NIT; it++) {
        int b = it & 1;
        if (it + 1 < NIT) {
            int nb = b ^ 1;
            int kt = (it + 1) * BK;
            if (STAGE == 1) {
#pragma unroll
                for (int j = 0; j < 4; j++)
                    cpa16(aS[nb] + aOff + j * 16, arowF + kt + j * 4);
            } else {
#pragma unroll
                for (int j = 0; j < 2; j++)
                    cpa16(aS[nb] + aOff + j * 16, arowH + kt + j * 8);
            }
            cpa16(bS[nb] + bOff0, wb + (size_t)(kt + br0) * ND + col0 + bc0);
            cpa16(bS[nb] + bOff1, wb + (size_t)(kt + br1) * ND + col0 + bc1);
            asm volatile("cp.async.commit_group;" ::: "memory");
            asm volatile("cp.async.wait_group 1;" ::: "memory");
        } else {
            asm volatile("cp.async.wait_group 0;" ::: "memory");
        }
        __syncthreads();

        const float*  AtF = (const float*)(dyn + b * ATB);
        const __half* AtH = (const __half*)(dyn + b * ATB);
        const float*  Bt  = (const float*)(dyn + 2 * ATB + b * BTB);

#pragma unroll
        for (int kk = 0; kk < BK; kk += 8) {
            uint32_t bf[4][2];
#pragma unroll
            for (int ni = 0; ni < 4; ni++) {
                const float* bp = Bt + (kk + tg) * LDB + wn + ni * 8 + g;
                bf[ni][0] = tf32u(bp[0]);
                bf[ni][1] = tf32u(bp[4 * LDB]);
            }
#pragma unroll
            for (int mi = 0; mi < 2; mi++) {
                uint32_t a0, a1, a2, a3;
                if (STAGE == 1) {
                    const float* ap = AtF + (wm + mi * 16 + g) * LDA1 + kk + tg;
                    a0 = tf32u(ap[0]);
                    a1 = tf32u(ap[8 * LDA1]);
                    a2 = tf32u(ap[4]);
                    a3 = tf32u(ap[8 * LDA1 + 4]);
                } else {
                    // fp16 values are exactly tf32-representable; fp32 bits ok
                    const __half* ap = AtH + (wm + mi * 16 + g) * LDA2 + kk + tg;
                    a0 = __float_as_uint(__half2float(ap[0]));
                    a1 = __float_as_uint(__half2float(ap[8 * LDA2]));
                    a2 = __float_as_uint(__half2float(ap[4]));
                    a3 = __float_as_uint(__half2float(ap[8 * LDA2 + 4]));
                }
#pragma unroll
                for (int ni = 0; ni < 4; ni++)
                    mma_tf32(acc[mi][ni][0], acc[mi][ni][1],
                             acc[mi][ni][2], acc[mi][ni][3],
                             a0, a1, a2, a3, bf[ni][0], bf[ni][1]);
            }
        }
        __syncthreads();
    }

    // ---- epilogue ----
#pragma unroll
    for (int mi = 0; mi < 2; mi++) {
        int r0 = wm + mi * 16 + g;
        int r1 = r0 + 8;
        bool ok0 = (row0 + r0) < cnt;
        bool ok1 = (row0 + r1) < cnt;
        if (STAGE == 1) {
            __half* p0 = g_h + (size_t)(base + row0 + r0) * HDIM + col0;
            __half* p1 = g_h + (size_t)(base + row0 + r1) * HDIM + col0;
#pragma unroll
            for (int ni = 0; ni < 4; ni++) {
                int c = wn + ni * 8 + tg * 2;
                if (ok0) *(__half2*)(p0 + c) = __floats2half2_rn(
                    gelu_exact(acc[mi][ni][0]), gelu_exact(acc[mi][ni][1]));
                if (ok1) *(__half2*)(p1 + c) = __floats2half2_rn(
                    gelu_exact(acc[mi][ni][2]), gelu_exact(acc[mi][ni][3]));
            }
        } else {
            int pid0 = ok0 ? g_list[e * NTOK + row0 + r0] : 0;
            int pid1 = ok1 ? g_list[e * NTOK + row0 + r1] : 0;
            float w0v = ok0 ? out[TP_OFF + pid0] : 0.f;
            float w1v = ok1 ? out[TP_OFF + pid1] : 0.f;
            float* o0 = out + OUT_OFF + (size_t)(pid0 >> 1) * DDIM + col0;
            float* o1 = out + OUT_OFF + (size_t)(pid1 >> 1) * DDIM + col0;
#pragma unroll
            for (int ni = 0; ni < 4; ni++) {
                int c = wn + ni * 8 + tg * 2;
                if (ok0) {
                    atomicAdd(o0 + c,     w0v * acc[mi][ni][0]);
                    atomicAdd(o0 + c + 1, w0v * acc[mi][ni][1]);
                }
                if (ok1) {
                    atomicAdd(o1 + c,     w1v * acc[mi][ni][2]);
                    atomicAdd(o1 + c + 1, w1v * acc[mi][ni][3]);
                }
            }
        }
    }
}

__global__ void aux_kernel(float* __restrict__ out) {
    if (threadIdx.x == 0) {
        float s = 0.f;
#pragma unroll
        for (int e = 0; e < NEXP; e++)
            s += ((float)g_count[e] / (float)NTOK) * (g_probsum[e] / (float)NTOK);
        out[AUX_OFF] = (float)NEXP * s;
    }
}

extern "C" void kernel_launch(void* const* d_in, const int* in_sizes, int n_in,
                              void* d_out, int out_size) {
    const float* x  = (const float*)d_in[0];   // [B,T,D]
    const float* gw = (const float*)d_in[1];   // [D,E]
    const float* w1 = (const float*)d_in[2];   // [E,D,H]
    const float* w2 = (const float*)d_in[3];   // [E,H,D]
    float* out = (float*)d_out;

    cudaFuncSetAttribute(mma_gemm<1>, cudaFuncAttributeMaxDynamicSharedMemorySize, DYN1);
    cudaFuncSetAttribute(mma_gemm<2>, cudaFuncAttributeMaxDynamicSharedMemorySize, DYN2);

    zero_kernel<<<1, 32>>>();
    zero_out_kernel<<<(unsigned)((OUT_SZ / 4 + 255) / 256), 256>>>(out);
    router_kernel<<<(NTOK * 32) / 256, 256>>>(x, gw, out);
    scan_kernel<<<1, 32>>>();

    mma_gemm<1><<<dim3(HDIM / 64, NTOK / 128, NEXP), 256, DYN1>>>(x, w1, out);
    mma_gemm<2><<<dim3(DDIM / 64, NTOK / 128, NEXP), 256, DYN2>>>(nullptr, w2, out);

    aux_kernel<<<1, 32>>>(out);
}